// round 2
// baseline (speedup 1.0000x reference)
#include <cuda_runtime.h>
#include <math.h>

// Problem constants
#define BATCH 2
#define CC    128      // feature channels
#define HH    48       // feature height
#define WF    160      // feature width
#define NYC   5        // corner grid Y
#define ND_   161
#define NW_   161
#define DD    160      // depth cells
#define WW    160      // width cells
#define KDIM  512      // C * (NY-1)
#define CH    512      // output channels
#define MROWS (BATCH*DD*WW)   // 51200

// Scratch (static device globals: no runtime allocation)
__device__ float g_integral[(size_t)BATCH*HH*WF*CC];        // NHWC layout, ~7.5 MB
__device__ float g_vox[(size_t)MROWS*KDIM];                 // ~100 MB

// ---------------------------------------------------------------------------
// Kernel 1a: cumsum along W, transpose NCHW -> NHWC
// ---------------------------------------------------------------------------
__global__ void k_cumsum_w(const float* __restrict__ feat) {
    int bh = blockIdx.x;            // 0..B*H-1
    int b = bh / HH, h = bh % HH;
    int c = threadIdx.x;            // 0..127
    const float* src = feat + ((size_t)(b*CC + c)*HH + h)*WF;
    float* dst = g_integral + ((size_t)(b*HH + h)*WF)*CC + c;
    float acc = 0.f;
    for (int w = 0; w < WF; w++) {
        acc += src[w];
        dst[(size_t)w*CC] = acc;
    }
}

// ---------------------------------------------------------------------------
// Kernel 1b: cumsum along H, in place on NHWC integral
// ---------------------------------------------------------------------------
__global__ void k_cumsum_h() {
    int bw = blockIdx.x;            // 0..B*W-1
    int b = bw / WF, w = bw % WF;
    int c = threadIdx.x;
    float* p = g_integral + (((size_t)b*HH)*WF + w)*CC + c;
    const size_t stride = (size_t)WF*CC;
    float acc = 0.f;
    for (int h = 0; h < HH; h++) {
        acc += p[h*stride];
        p[h*stride] = acc;
    }
}

// ---------------------------------------------------------------------------
// Kernel 2: project corners, build bbox, 4-corner box-sum sampling.
// One cell = (b, y, d, w); 128 threads = channels; 2 cells / 256-thr block.
// ---------------------------------------------------------------------------
__device__ __forceinline__ void project_pt(const float* __restrict__ cal,
                                           float X, float Y, float Z,
                                           float& nx, float& ny) {
    float h0 = cal[0]*X + cal[1]*Y + cal[2]*Z  + cal[3];
    float h1 = cal[4]*X + cal[5]*Y + cal[6]*Z  + cal[7];
    float h2 = cal[8]*X + cal[9]*Y + cal[10]*Z + cal[11];
    float ix = h0 / h2;
    float iy = h1 / h2;
    nx = fminf(fmaxf(2.0f*ix/(float)WF - 1.0f, -1.f), 1.f);
    ny = fminf(fmaxf(2.0f*iy/(float)HH - 1.0f, -1.f), 1.f);
}

__device__ __forceinline__ float bilin_sample(int b, int c, float px, float py) {
    float gx = (px + 1.f)*((float)WF*0.5f) - 0.5f;
    float gy = (py + 1.f)*((float)HH*0.5f) - 0.5f;
    float x0f = floorf(gx), y0f = floorf(gy);
    float wx = gx - x0f, wy = gy - y0f;
    int ix = (int)x0f, iy = (int)y0f;
    float v = 0.f;
    #pragma unroll
    for (int dy = 0; dy < 2; dy++) {
        int yy = iy + dy;
        if (yy < 0 || yy >= HH) continue;
        float fy = dy ? wy : (1.f - wy);
        #pragma unroll
        for (int dx = 0; dx < 2; dx++) {
            int xx = ix + dx;
            if (xx < 0 || xx >= WF) continue;
            float fx = dx ? wx : (1.f - wx);
            v += g_integral[((size_t)(b*HH + yy)*WF + xx)*CC + c] * fx * fy;
        }
    }
    return v;
}

__global__ __launch_bounds__(256) void k_sample(const float* __restrict__ calib,
                                                const float* __restrict__ corners) {
    int cell = blockIdx.x*2 + (threadIdx.x >> 7);   // 0..204799
    int c = threadIdx.x & 127;
    int w = cell % WW;
    int d = (cell / WW) % DD;
    int y = (cell / (WW*DD)) & 3;
    int b = cell / (WW*DD*4);
    const float* cal = calib + b*12;

    float ax, ay, bx, by, cx2, cy2, dx2, dy2;
    {
        const float* p = corners + (((size_t)y*ND_ + d)*NW_ + w)*3;
        project_pt(cal, p[0], p[1], p[2], ax, ay);
    }
    {
        const float* p = corners + (((size_t)y*ND_ + (d+1))*NW_ + w)*3;
        project_pt(cal, p[0], p[1], p[2], bx, by);
    }
    {
        const float* p = corners + (((size_t)(y+1)*ND_ + (d+1))*NW_ + (w+1))*3;
        project_pt(cal, p[0], p[1], p[2], cx2, cy2);
    }
    {
        const float* p = corners + (((size_t)(y+1)*ND_ + d)*NW_ + (w+1))*3;
        project_pt(cal, p[0], p[1], p[2], dx2, dy2);
    }

    float x0 = fminf(ax, bx),  y0v = fminf(ay, by);
    float x1 = fmaxf(cx2, dx2), y1v = fmaxf(cy2, dy2);

    float area = (x1 - x0) * (y1v - y0v) * ((float)HH * (float)WF * 0.25f) + 1e-6f;
    float vis  = (area > 1e-6f) ? 1.f : 0.f;

    float acc = bilin_sample(b, c, x0, y0v)
              + bilin_sample(b, c, x1, y1v)
              - bilin_sample(b, c, x1, y0v)
              - bilin_sample(b, c, x0, y1v);

    float val = acc / area * vis;

    int row = (b*WW + w)*DD + d;                // rows ordered (b, w, d)
    g_vox[(size_t)row*KDIM + y*CC + c] = val;   // K index = y*128 + c
}

// ---------------------------------------------------------------------------
// Kernel 3: GEMM  out = relu(vox @ W_perm + bias), fused output transpose.
// Double-buffered smem pipeline: prefetch tile k+1 to registers while
// computing tile k; one __syncthreads per K-step.
// ---------------------------------------------------------------------------
#define BM 128
#define BN 128
#define BK 16

__global__ __launch_bounds__(256, 2) void k_gemm(const float* __restrict__ Wl,
                                                 const float* __restrict__ bias,
                                                 float* __restrict__ out) {
    __shared__ float As[2][BK][BM];
    __shared__ float Bs[2][BK][BN];

    const int m0 = blockIdx.x * BM;   // 400 blocks
    const int n0 = blockIdx.y * BN;   // 4 blocks
    const int tid = threadIdx.x;
    const int tx = tid & 15;          // n direction
    const int ty = tid >> 4;          // m direction

    // A-load addressing (per thread: 2 float4)
    const int a_row0 = tid >> 2;              // 0..63 (then +64)
    const int a_c4   = (tid & 3) * 4;         // 0,4,8,12
    // B-load addressing (per thread: 2 float4)
    const int b_kr0  = tid >> 5;              // 0..7 (then +8)
    const int b_cn   = (tid & 31) * 4;        // 0..124

    float acc[8][8];
    #pragma unroll
    for (int i = 0; i < 8; i++)
        #pragma unroll
        for (int j = 0; j < 8; j++) acc[i][j] = 0.f;

    // ---- load first tile (k0 = 0) into buffer 0 ----
    {
        #pragma unroll
        for (int i = 0; i < 2; i++) {
            int row = a_row0 + i*64;
            float4 v = *(const float4*)(g_vox + (size_t)(m0 + row)*KDIM + a_c4);
            As[0][a_c4+0][row] = v.x; As[0][a_c4+1][row] = v.y;
            As[0][a_c4+2][row] = v.z; As[0][a_c4+3][row] = v.w;
        }
        #pragma unroll
        for (int i = 0; i < 2; i++) {
            int kr = b_kr0 + i*8;
            int kk = kr;
            int wrow = ((kk & 127) << 2) + (kk >> 7);   // c*4 + y
            float4 v = *(const float4*)(Wl + (size_t)wrow*CH + n0 + b_cn);
            *(float4*)&Bs[0][kr][b_cn] = v;
        }
    }
    __syncthreads();

    int buf = 0;
    for (int k0 = 0; k0 < KDIM; k0 += BK) {
        // ---- prefetch next tile into registers ----
        float4 pa[2], pb[2];
        const bool has_next = (k0 + BK) < KDIM;
        if (has_next) {
            int kn = k0 + BK;
            #pragma unroll
            for (int i = 0; i < 2; i++) {
                int row = a_row0 + i*64;
                pa[i] = *(const float4*)(g_vox + (size_t)(m0 + row)*KDIM + kn + a_c4);
            }
            #pragma unroll
            for (int i = 0; i < 2; i++) {
                int kk = kn + b_kr0 + i*8;
                int wrow = ((kk & 127) << 2) + (kk >> 7);
                pb[i] = *(const float4*)(Wl + (size_t)wrow*CH + n0 + b_cn);
            }
        }

        // ---- compute on current buffer ----
        #pragma unroll
        for (int k = 0; k < BK; k++) {
            float a[8], bb[8];
            #pragma unroll
            for (int i = 0; i < 8; i++) a[i]  = As[buf][k][ty*8 + i];
            #pragma unroll
            for (int j = 0; j < 8; j++) bb[j] = Bs[buf][k][tx*8 + j];
            #pragma unroll
            for (int i = 0; i < 8; i++)
                #pragma unroll
                for (int j = 0; j < 8; j++)
                    acc[i][j] += a[i] * bb[j];
        }

        // ---- store prefetched tile into the other buffer ----
        if (has_next) {
            int nb = buf ^ 1;
            #pragma unroll
            for (int i = 0; i < 2; i++) {
                int row = a_row0 + i*64;
                As[nb][a_c4+0][row] = pa[i].x; As[nb][a_c4+1][row] = pa[i].y;
                As[nb][a_c4+2][row] = pa[i].z; As[nb][a_c4+3][row] = pa[i].w;
            }
            #pragma unroll
            for (int i = 0; i < 2; i++) {
                int kr = b_kr0 + i*8;
                *(float4*)&Bs[nb][kr][b_cn] = pb[i];
            }
            __syncthreads();
            buf = nb;
        }
    }

    // Epilogue: bias + relu + transpose-store
    #pragma unroll
    for (int j = 0; j < 8; j++) {
        int n = n0 + tx*8 + j;
        float bv = bias[n];
        #pragma unroll
        for (int i = 0; i < 8; i++) {
            int m = m0 + ty*8 + i;
            int bidx = m / (WW*DD);
            int moff = m - bidx*(WW*DD);      // = w*160 + d
            float v = acc[i][j] + bv;
            out[(size_t)(bidx*CH + n)*(WW*DD) + moff] = fmaxf(v, 0.f);
        }
    }
}

// ---------------------------------------------------------------------------
extern "C" void kernel_launch(void* const* d_in, const int* in_sizes, int n_in,
                              void* d_out, int out_size) {
    const float* features = (const float*)d_in[0];   // [2,128,48,160]
    const float* calib    = (const float*)d_in[1];   // [2,3,4]
    const float* corners  = (const float*)d_in[2];   // [1,5,161,161,3]
    const float* W_lin    = (const float*)d_in[3];   // [512,512]
    const float* b_lin    = (const float*)d_in[4];   // [512]
    float* out = (float*)d_out;                      // [2,512,160,160]

    k_cumsum_w<<<BATCH*HH, CC>>>(features);
    k_cumsum_h<<<BATCH*WF, CC>>>();
    k_sample<<<(BATCH*4*DD*WW)/2, 256>>>(calib, corners);
    k_gemm<<<dim3(MROWS/BM, CH/BN), 256>>>(W_lin, b_lin, out);
}

// round 3
// speedup vs baseline: 2.7469x; 2.7469x over previous
#include <cuda_runtime.h>
#include <math.h>
#include <stdint.h>

// Problem constants
#define BATCH 2
#define CC    128
#define HH    48
#define WF    160
#define ND_   161
#define NW_   161
#define DD    160
#define WW    160
#define KDIM  512
#define CH    512
#define MROWS (BATCH*DD*WW)     // 51200
#define NCELL (BATCH*4*DD*WW)   // 204800
#define PLANE (WW*DD)           // 25600

// Static device scratch
__device__ float g_integral[(size_t)BATCH*HH*WF*CC];   // NHWC
__device__ float g_vox[(size_t)MROWS*KDIM];            // tf32-rounded values
__device__ float g_wl[(size_t)KDIM*CH];                // permuted + tf32-rounded W
__device__ int   g_tidx[(size_t)NCELL*16];
__device__ float g_tw[(size_t)NCELL*16];

__device__ __forceinline__ uint32_t f2tf32(float f) {
    uint32_t r;
    asm("cvt.rna.tf32.f32 %0, %1;" : "=r"(r) : "f"(f));
    return r;
}

// ---------------------------------------------------------------------------
// cumsum along W, transpose NCHW -> NHWC
// ---------------------------------------------------------------------------
__global__ void k_cumsum_w(const float* __restrict__ feat) {
    int bh = blockIdx.x;
    int b = bh / HH, h = bh % HH;
    int c = threadIdx.x;
    const float* src = feat + ((size_t)(b*CC + c)*HH + h)*WF;
    float* dst = g_integral + ((size_t)(b*HH + h)*WF)*CC + c;
    float acc = 0.f;
    for (int w = 0; w < WF; w++) {
        acc += src[w];
        dst[(size_t)w*CC] = acc;
    }
}

// cumsum along H in place
__global__ void k_cumsum_h() {
    int bw = blockIdx.x;
    int b = bw / WF, w = bw % WF;
    int c = threadIdx.x;
    float* p = g_integral + (((size_t)b*HH)*WF + w)*CC + c;
    const size_t stride = (size_t)WF*CC;
    float acc = 0.f;
    for (int h = 0; h < HH; h++) {
        acc += p[h*stride];
        p[h*stride] = acc;
    }
}

// ---------------------------------------------------------------------------
// W permute + tf32 round:  g_wl[kk][n] = tf32(W_lin[(kk&127)*4 + (kk>>7)][n])
// ---------------------------------------------------------------------------
__global__ void k_wperm(const float* __restrict__ Wl) {
    int i = blockIdx.x*256 + threadIdx.x;       // 0..262143
    int kk = i >> 9;
    int n  = i & 511;
    int wrow = ((kk & 127) << 2) + (kk >> 7);
    g_wl[i] = __uint_as_float(f2tf32(Wl[(size_t)wrow*CH + n]));
}

// ---------------------------------------------------------------------------
// Per-cell bbox + 16 bilinear taps (index, weight) precompute. 1 thread/cell.
// ---------------------------------------------------------------------------
__device__ __forceinline__ void project_pt(const float* __restrict__ cal,
                                           float X, float Y, float Z,
                                           float& nx, float& ny) {
    float h0 = cal[0]*X + cal[1]*Y + cal[2]*Z  + cal[3];
    float h1 = cal[4]*X + cal[5]*Y + cal[6]*Z  + cal[7];
    float h2 = cal[8]*X + cal[9]*Y + cal[10]*Z + cal[11];
    float ix = h0 / h2;
    float iy = h1 / h2;
    nx = fminf(fmaxf(2.0f*ix/(float)WF - 1.0f, -1.f), 1.f);
    ny = fminf(fmaxf(2.0f*iy/(float)HH - 1.0f, -1.f), 1.f);
}

__global__ void k_bbox(const float* __restrict__ calib,
                       const float* __restrict__ corners) {
    int cell = blockIdx.x*256 + threadIdx.x;
    if (cell >= NCELL) return;
    int w = cell % WW;
    int d = (cell / WW) % DD;
    int y = (cell / (WW*DD)) & 3;
    int b = cell / (WW*DD*4);
    const float* cal = calib + b*12;

    float ax, ay, bx, by, cx2, cy2, dx2, dy2;
    { const float* p = corners + (((size_t)y*ND_ + d)*NW_ + w)*3;
      project_pt(cal, p[0], p[1], p[2], ax, ay); }
    { const float* p = corners + (((size_t)y*ND_ + (d+1))*NW_ + w)*3;
      project_pt(cal, p[0], p[1], p[2], bx, by); }
    { const float* p = corners + (((size_t)(y+1)*ND_ + (d+1))*NW_ + (w+1))*3;
      project_pt(cal, p[0], p[1], p[2], cx2, cy2); }
    { const float* p = corners + (((size_t)(y+1)*ND_ + d)*NW_ + (w+1))*3;
      project_pt(cal, p[0], p[1], p[2], dx2, dy2); }

    float x0 = fminf(ax, bx),   y0v = fminf(ay, by);
    float x1 = fmaxf(cx2, dx2), y1v = fmaxf(cy2, dy2);

    float area = (x1 - x0) * (y1v - y0v) * ((float)HH * (float)WF * 0.25f) + 1e-6f;
    float vis  = (area > 1e-6f) ? 1.f : 0.f;
    float inv  = vis / area;

    float sx[4] = {x0, x1, x1, x0};
    float sy[4] = {y0v, y1v, y0v, y1v};
    float sg[4] = {1.f, 1.f, -1.f, -1.f};

    int   base = cell*16;
    #pragma unroll
    for (int s = 0; s < 4; s++) {
        float gx = (sx[s] + 1.f)*((float)WF*0.5f) - 0.5f;
        float gy = (sy[s] + 1.f)*((float)HH*0.5f) - 0.5f;
        float x0f = floorf(gx), y0f = floorf(gy);
        float wx = gx - x0f, wy = gy - y0f;
        int ix = (int)x0f, iy = (int)y0f;
        float fw[4] = {(1.f-wx)*(1.f-wy), wx*(1.f-wy), (1.f-wx)*wy, wx*wy};
        int   tx[4] = {ix, ix+1, ix, ix+1};
        int   ty[4] = {iy, iy, iy+1, iy+1};
        #pragma unroll
        for (int t = 0; t < 4; t++) {
            int xx = tx[t], yy = ty[t];
            bool valid = (xx >= 0) & (xx < WF) & (yy >= 0) & (yy < HH);
            g_tidx[base + s*4 + t] = valid ? ((b*HH + yy)*WF + xx)*CC : 0;
            g_tw  [base + s*4 + t] = valid ? sg[s]*fw[t]*inv : 0.f;
        }
    }
}

// ---------------------------------------------------------------------------
// Sampler: per (cell, channel) 16 weighted gathers. Writes tf32-rounded vox.
// ---------------------------------------------------------------------------
__global__ __launch_bounds__(256) void k_sample() {
    int cell = blockIdx.x*2 + (threadIdx.x >> 7);
    int c = threadIdx.x & 127;
    int base = cell*16;

    int   idx[16];
    float wgt[16];
    #pragma unroll
    for (int i = 0; i < 16; i++) {
        idx[i] = __ldg(&g_tidx[base+i]);
        wgt[i] = __ldg(&g_tw[base+i]);
    }
    float acc = 0.f;
    #pragma unroll
    for (int i = 0; i < 16; i++)
        acc += wgt[i] * g_integral[idx[i] + c];

    int w = cell % WW;
    int d = (cell / WW) % DD;
    int y = (cell / (WW*DD)) & 3;
    int b = cell / (WW*DD*4);
    int row = (b*WW + w)*DD + d;
    g_vox[(size_t)row*KDIM + y*CC + c] = __uint_as_float(f2tf32(acc));
}

// ---------------------------------------------------------------------------
// tf32 tensor-core GEMM: out = relu(vox @ g_wl + bias), fused transpose.
// 128x128x16 tile, 256 threads (2x4 warps, 64x32 per warp), cp.async
// double-buffered smem, mma.sync.m16n8k8.tf32.
// ---------------------------------------------------------------------------
#define BM 128
#define BN 128
#define BK 16
#define AS_STRIDE 20
#define BS_STRIDE 136

__device__ __forceinline__ void cp16(uint32_t smem, const void* gmem) {
    asm volatile("cp.async.ca.shared.global [%0], [%1], 16;\n" :: "r"(smem), "l"(gmem));
}
__device__ __forceinline__ void cp_commit() {
    asm volatile("cp.async.commit_group;\n" ::: "memory");
}
__device__ __forceinline__ void cp_wait0() {
    asm volatile("cp.async.wait_group 0;\n" ::: "memory");
}
__device__ __forceinline__ void mma_tf32(float* c, const uint32_t* a, const uint32_t* b) {
    asm volatile(
        "mma.sync.aligned.m16n8k8.row.col.f32.tf32.tf32.f32 "
        "{%0,%1,%2,%3}, {%4,%5,%6,%7}, {%8,%9}, {%0,%1,%2,%3};\n"
        : "+f"(c[0]), "+f"(c[1]), "+f"(c[2]), "+f"(c[3])
        : "r"(a[0]), "r"(a[1]), "r"(a[2]), "r"(a[3]), "r"(b[0]), "r"(b[1]));
}

__global__ __launch_bounds__(256, 2) void k_gemm(const float* __restrict__ bias,
                                                 float* __restrict__ out) {
    __shared__ uint32_t As[2][BM][AS_STRIDE];   // [m][k], pad 20
    __shared__ uint32_t Bs[2][BK][BS_STRIDE];   // [k][n], pad 136

    const int m0 = blockIdx.x * BM;
    const int n0 = blockIdx.y * BN;
    const int tid = threadIdx.x;
    const int wid = tid >> 5;
    const int lane = tid & 31;
    const int g  = lane >> 2;
    const int tg = lane & 3;
    const int warp_m = wid >> 2;       // 0..1
    const int warp_n = wid & 3;        // 0..3
    const int mbase = warp_m * 64;
    const int nbase = warp_n * 32;

    // cp.async addressing (per thread: 2 A chunks + 2 B chunks of 16B)
    const int a_row = tid >> 2;              // 0..63 (+64)
    const int a_c4  = (tid & 3) * 4;
    const int b_kr  = tid >> 5;              // 0..7 (+8)
    const int b_n4  = (tid & 31) * 4;

    uint32_t asA[2][2], asB[2][2];
    #pragma unroll
    for (int buf = 0; buf < 2; buf++) {
        #pragma unroll
        for (int i = 0; i < 2; i++) {
            asA[buf][i] = (uint32_t)__cvta_generic_to_shared(&As[buf][a_row + i*64][a_c4]);
            asB[buf][i] = (uint32_t)__cvta_generic_to_shared(&Bs[buf][b_kr + i*8][b_n4]);
        }
    }

    float acc[4][4][4];
    #pragma unroll
    for (int mi = 0; mi < 4; mi++)
        #pragma unroll
        for (int ni = 0; ni < 4; ni++)
            #pragma unroll
            for (int r = 0; r < 4; r++) acc[mi][ni][r] = 0.f;

    // prologue: tile 0 -> buf 0
    #pragma unroll
    for (int i = 0; i < 2; i++) {
        cp16(asA[0][i], g_vox + (size_t)(m0 + a_row + i*64)*KDIM + a_c4);
        cp16(asB[0][i], g_wl  + (size_t)(b_kr + i*8)*CH + n0 + b_n4);
    }
    cp_commit();
    cp_wait0();
    __syncthreads();

    int buf = 0;
    for (int k0 = 0; k0 < KDIM; k0 += BK) {
        const bool has_next = (k0 + BK) < KDIM;
        if (has_next) {
            int kn = k0 + BK;
            int nb = buf ^ 1;
            #pragma unroll
            for (int i = 0; i < 2; i++) {
                cp16(asA[nb][i], g_vox + (size_t)(m0 + a_row + i*64)*KDIM + kn + a_c4);
                cp16(asB[nb][i], g_wl  + (size_t)(kn + b_kr + i*8)*CH + n0 + b_n4);
            }
            cp_commit();
        }

        #pragma unroll
        for (int kc = 0; kc < BK; kc += 8) {
            uint32_t a[4][4], b[4][2];
            #pragma unroll
            for (int mi = 0; mi < 4; mi++) {
                int r0 = mbase + mi*16 + g;
                a[mi][0] = As[buf][r0    ][kc + tg];
                a[mi][1] = As[buf][r0 + 8][kc + tg];
                a[mi][2] = As[buf][r0    ][kc + tg + 4];
                a[mi][3] = As[buf][r0 + 8][kc + tg + 4];
            }
            #pragma unroll
            for (int ni = 0; ni < 4; ni++) {
                int cn = nbase + ni*8 + g;
                b[ni][0] = Bs[buf][kc + tg    ][cn];
                b[ni][1] = Bs[buf][kc + tg + 4][cn];
            }
            #pragma unroll
            for (int mi = 0; mi < 4; mi++)
                #pragma unroll
                for (int ni = 0; ni < 4; ni++)
                    mma_tf32(acc[mi][ni], a[mi], b[ni]);
        }

        if (has_next) {
            cp_wait0();
            __syncthreads();
            buf ^= 1;
        }
    }

    // Epilogue: bias + relu + transposed store
    const int bidx  = m0 / PLANE;
    const int mrel0 = m0 - bidx*PLANE + mbase;   // w*160+d offset base
    #pragma unroll
    for (int ni = 0; ni < 4; ni++) {
        int n_e = n0 + nbase + ni*8 + 2*tg;
        float be = bias[n_e];
        float bo = bias[n_e + 1];
        float* ope = out + ((size_t)(bidx*CH + n_e))*PLANE;
        float* opo = ope + PLANE;
        #pragma unroll
        for (int mi = 0; mi < 4; mi++) {
            int moff = mrel0 + mi*16 + g;
            ope[moff    ] = fmaxf(acc[mi][ni][0] + be, 0.f);
            opo[moff    ] = fmaxf(acc[mi][ni][1] + bo, 0.f);
            ope[moff + 8] = fmaxf(acc[mi][ni][2] + be, 0.f);
            opo[moff + 8] = fmaxf(acc[mi][ni][3] + bo, 0.f);
        }
    }
}

// ---------------------------------------------------------------------------
extern "C" void kernel_launch(void* const* d_in, const int* in_sizes, int n_in,
                              void* d_out, int out_size) {
    const float* features = (const float*)d_in[0];   // [2,128,48,160]
    const float* calib    = (const float*)d_in[1];   // [2,3,4]
    const float* corners  = (const float*)d_in[2];   // [1,5,161,161,3]
    const float* W_lin    = (const float*)d_in[3];   // [512,512]
    const float* b_lin    = (const float*)d_in[4];   // [512]
    float* out = (float*)d_out;                      // [2,512,160,160]

    k_cumsum_w<<<BATCH*HH, CC>>>(features);
    k_cumsum_h<<<BATCH*WF, CC>>>();
    k_wperm<<<(KDIM*CH)/256, 256>>>(W_lin);
    k_bbox<<<NCELL/256, 256>>>(calib, corners);
    k_sample<<<NCELL/2, 256>>>();
    k_gemm<<<dim3(MROWS/BM, CH/BN), 256>>>(b_lin, out);
}

// round 4
// speedup vs baseline: 3.0615x; 1.1145x over previous
#include <cuda_runtime.h>
#include <math.h>
#include <stdint.h>

// Problem constants
#define BATCH 2
#define CC    128
#define HH    48
#define WF    160
#define ND_   161
#define NW_   161
#define DD    160
#define WW    160
#define KDIM  512
#define CH    512
#define MROWS (BATCH*DD*WW)     // 51200
#define NCELL (BATCH*4*DD*WW)   // 204800
#define PLANE (WW*DD)           // 25600

// Static device scratch
__device__ float g_integral[(size_t)BATCH*HH*WF*CC];   // NHWC
__device__ float g_vox[(size_t)MROWS*KDIM];            // tf32-rounded
__device__ float g_wl[(size_t)KDIM*CH];                // permuted + tf32-rounded
__device__ int   g_tidx[(size_t)16*NCELL];             // SoA: [tap][cell]
__device__ float g_tw[(size_t)16*NCELL];               // SoA: [tap][cell]

__device__ __forceinline__ uint32_t f2tf32(float f) {
    uint32_t r;
    asm("cvt.rna.tf32.f32 %0, %1;" : "=r"(r) : "f"(f));
    return r;
}

// ---------------------------------------------------------------------------
// cumsum along W + transpose NCHW -> NHWC, via smem tile.
// One block per (b, h, channel-half): 64 channels x 160 w.
// ---------------------------------------------------------------------------
__global__ __launch_bounds__(256) void k_cumsum_w(const float* __restrict__ feat) {
    __shared__ float S[64][WF + 1];
    int blk = blockIdx.x;                 // 0..191
    int b    = blk / (HH*2);
    int rem  = blk % (HH*2);
    int h    = rem >> 1;
    int c0   = (rem & 1) * 64;
    int tid  = threadIdx.x;

    // load: coalesced along w
    #pragma unroll
    for (int i = 0; i < 40; i++) {
        int idx = i*256 + tid;            // 0..10239
        int c = idx / WF;
        int w = idx - c*WF;
        S[c][w] = feat[((size_t)(b*CC + c0 + c)*HH + h)*WF + w];
    }
    __syncthreads();
    // serial scan per channel
    if (tid < 64) {
        float acc = 0.f;
        #pragma unroll 8
        for (int w = 0; w < WF; w++) { acc += S[tid][w]; S[tid][w] = acc; }
    }
    __syncthreads();
    // store: coalesced along c
    #pragma unroll
    for (int i = 0; i < 40; i++) {
        int idx = i*256 + tid;
        int w = idx >> 6;
        int c = idx & 63;
        g_integral[((size_t)(b*HH + h)*WF + w)*CC + c0 + c] = S[c][w];
    }
}

// cumsum along H in place (coalesced along c in NHWC)
__global__ void k_cumsum_h() {
    int bw = blockIdx.x;
    int b = bw / WF, w = bw % WF;
    int c = threadIdx.x;
    float* p = g_integral + (((size_t)b*HH)*WF + w)*CC + c;
    const size_t stride = (size_t)WF*CC;
    float acc = 0.f;
    #pragma unroll 6
    for (int h = 0; h < HH; h++) {
        acc += p[h*stride];
        p[h*stride] = acc;
    }
}

// ---------------------------------------------------------------------------
// W permute + tf32 round
// ---------------------------------------------------------------------------
__global__ void k_wperm(const float* __restrict__ Wl) {
    int i = blockIdx.x*256 + threadIdx.x;
    int kk = i >> 9;
    int n  = i & 511;
    int wrow = ((kk & 127) << 2) + (kk >> 7);
    g_wl[i] = __uint_as_float(f2tf32(Wl[(size_t)wrow*CH + n]));
}

// ---------------------------------------------------------------------------
// Per-cell bbox + 16 taps, SoA output (coalesced writes).
// ---------------------------------------------------------------------------
__device__ __forceinline__ void project_pt(const float* __restrict__ cal,
                                           float X, float Y, float Z,
                                           float& nx, float& ny) {
    float h0 = cal[0]*X + cal[1]*Y + cal[2]*Z  + cal[3];
    float h1 = cal[4]*X + cal[5]*Y + cal[6]*Z  + cal[7];
    float h2 = cal[8]*X + cal[9]*Y + cal[10]*Z + cal[11];
    float ix = h0 / h2;
    float iy = h1 / h2;
    nx = fminf(fmaxf(2.0f*ix/(float)WF - 1.0f, -1.f), 1.f);
    ny = fminf(fmaxf(2.0f*iy/(float)HH - 1.0f, -1.f), 1.f);
}

__global__ void k_bbox(const float* __restrict__ calib,
                       const float* __restrict__ corners) {
    int cell = blockIdx.x*256 + threadIdx.x;
    if (cell >= NCELL) return;
    int w = cell % WW;
    int d = (cell / WW) % DD;
    int y = (cell / (WW*DD)) & 3;
    int b = cell / (WW*DD*4);
    const float* cal = calib + b*12;

    float ax, ay, bx, by, cx2, cy2, dx2, dy2;
    { const float* p = corners + (((size_t)y*ND_ + d)*NW_ + w)*3;
      project_pt(cal, p[0], p[1], p[2], ax, ay); }
    { const float* p = corners + (((size_t)y*ND_ + (d+1))*NW_ + w)*3;
      project_pt(cal, p[0], p[1], p[2], bx, by); }
    { const float* p = corners + (((size_t)(y+1)*ND_ + (d+1))*NW_ + (w+1))*3;
      project_pt(cal, p[0], p[1], p[2], cx2, cy2); }
    { const float* p = corners + (((size_t)(y+1)*ND_ + d)*NW_ + (w+1))*3;
      project_pt(cal, p[0], p[1], p[2], dx2, dy2); }

    float x0 = fminf(ax, bx),   y0v = fminf(ay, by);
    float x1 = fmaxf(cx2, dx2), y1v = fmaxf(cy2, dy2);

    float area = (x1 - x0) * (y1v - y0v) * ((float)HH * (float)WF * 0.25f) + 1e-6f;
    float vis  = (area > 1e-6f) ? 1.f : 0.f;
    float inv  = vis / area;

    float sx[4] = {x0, x1, x1, x0};
    float sy[4] = {y0v, y1v, y0v, y1v};
    float sg[4] = {1.f, 1.f, -1.f, -1.f};

    #pragma unroll
    for (int s = 0; s < 4; s++) {
        float gx = (sx[s] + 1.f)*((float)WF*0.5f) - 0.5f;
        float gy = (sy[s] + 1.f)*((float)HH*0.5f) - 0.5f;
        float x0f = floorf(gx), y0f = floorf(gy);
        float wx = gx - x0f, wy = gy - y0f;
        int ix = (int)x0f, iy = (int)y0f;
        float fw[4] = {(1.f-wx)*(1.f-wy), wx*(1.f-wy), (1.f-wx)*wy, wx*wy};
        int   tx[4] = {ix, ix+1, ix, ix+1};
        int   ty[4] = {iy, iy, iy+1, iy+1};
        #pragma unroll
        for (int t = 0; t < 4; t++) {
            int xx = tx[t], yy = ty[t];
            bool valid = (xx >= 0) & (xx < WF) & (yy >= 0) & (yy < HH);
            g_tidx[(size_t)(s*4 + t)*NCELL + cell] = valid ? ((b*HH + yy)*WF + xx)*CC : 0;
            g_tw  [(size_t)(s*4 + t)*NCELL + cell] = valid ? sg[s]*fw[t]*inv : 0.f;
        }
    }
}

// ---------------------------------------------------------------------------
// Sampler: per (cell, channel) 16 weighted gathers. Writes tf32-rounded vox.
// ---------------------------------------------------------------------------
__global__ __launch_bounds__(256) void k_sample() {
    int cell = blockIdx.x*2 + (threadIdx.x >> 7);
    int c = threadIdx.x & 127;

    int   idx[16];
    float wgt[16];
    #pragma unroll
    for (int i = 0; i < 16; i++) {
        idx[i] = __ldg(&g_tidx[(size_t)i*NCELL + cell]);
        wgt[i] = __ldg(&g_tw[(size_t)i*NCELL + cell]);
    }
    float acc = 0.f;
    #pragma unroll
    for (int i = 0; i < 16; i++)
        acc += wgt[i] * g_integral[idx[i] + c];

    int w = cell % WW;
    int d = (cell / WW) % DD;
    int y = (cell / (WW*DD)) & 3;
    int b = cell / (WW*DD*4);
    int row = (b*WW + w)*DD + d;
    g_vox[(size_t)row*KDIM + y*CC + c] = __uint_as_float(f2tf32(acc));
}

// ---------------------------------------------------------------------------
// tf32 tensor-core GEMM: out = relu(vox @ g_wl + bias), fused transpose.
// 128x128x32 tile, 256 threads (2x4 warps, 64x32/warp), cp.async double
// buffer, mma.sync.m16n8k8.tf32. Dynamic smem (~70 KB).
// ---------------------------------------------------------------------------
#define BM 128
#define BN 128
#define BK 32
#define AS_STRIDE 36    // floats; 144B rows (16B aligned); banks 4g+tg distinct
#define BS_STRIDE 136   // floats; banks 8tg+g distinct
#define A_BUF_ELEMS (BM*AS_STRIDE)
#define B_BUF_ELEMS (BK*BS_STRIDE)
#define GEMM_SMEM_BYTES ((2*A_BUF_ELEMS + 2*B_BUF_ELEMS)*4)

__device__ __forceinline__ void cp16(uint32_t smem, const void* gmem) {
    asm volatile("cp.async.ca.shared.global [%0], [%1], 16;\n" :: "r"(smem), "l"(gmem));
}
__device__ __forceinline__ void cp_commit() {
    asm volatile("cp.async.commit_group;\n" ::: "memory");
}
__device__ __forceinline__ void cp_wait0() {
    asm volatile("cp.async.wait_group 0;\n" ::: "memory");
}
__device__ __forceinline__ void mma_tf32(float* c, const uint32_t* a, const uint32_t* b) {
    asm volatile(
        "mma.sync.aligned.m16n8k8.row.col.f32.tf32.tf32.f32 "
        "{%0,%1,%2,%3}, {%4,%5,%6,%7}, {%8,%9}, {%0,%1,%2,%3};\n"
        : "+f"(c[0]), "+f"(c[1]), "+f"(c[2]), "+f"(c[3])
        : "r"(a[0]), "r"(a[1]), "r"(a[2]), "r"(a[3]), "r"(b[0]), "r"(b[1]));
}

__global__ __launch_bounds__(256, 2) void k_gemm(const float* __restrict__ bias,
                                                 float* __restrict__ out) {
    extern __shared__ __align__(16) uint32_t dynsmem[];
    uint32_t* Asm = dynsmem;                      // [2][BM][AS_STRIDE]
    uint32_t* Bsm = dynsmem + 2*A_BUF_ELEMS;      // [2][BK][BS_STRIDE]

    const int n0 = blockIdx.x * BN;   // 4 blocks (fast axis -> A-sharing CTAs adjacent)
    const int m0 = blockIdx.y * BM;   // 400 blocks
    const int tid = threadIdx.x;
    const int wid = tid >> 5;
    const int lane = tid & 31;
    const int g  = lane >> 2;
    const int tg = lane & 3;
    const int mbase = (wid >> 2) * 64;
    const int nbase = (wid & 3) * 32;

    // cp.async addressing: A: 4 float4/thread; B: 4 float4/thread
    const int a_row0 = tid >> 3;              // 0..31 (+i*32)
    const int a_cf   = (tid & 7) * 4;         // float col 0..28
    const int b_kr0  = tid >> 5;              // 0..7 (+i*8)
    const int b_n4   = (tid & 31) * 4;

    float acc[4][4][4];
    #pragma unroll
    for (int mi = 0; mi < 4; mi++)
        #pragma unroll
        for (int ni = 0; ni < 4; ni++)
            #pragma unroll
            for (int r = 0; r < 4; r++) acc[mi][ni][r] = 0.f;

    // smem byte addresses
    uint32_t asA = (uint32_t)__cvta_generic_to_shared(Asm);
    uint32_t asB = (uint32_t)__cvta_generic_to_shared(Bsm);

    // prologue: tile 0 -> buf 0
    #pragma unroll
    for (int i = 0; i < 4; i++) {
        int row = a_row0 + i*32;
        cp16(asA + (row*AS_STRIDE + a_cf)*4,
             g_vox + (size_t)(m0 + row)*KDIM + a_cf);
        int kr = b_kr0 + i*8;
        cp16(asB + (kr*BS_STRIDE + b_n4)*4,
             g_wl + (size_t)kr*CH + n0 + b_n4);
    }
    cp_commit();
    cp_wait0();
    __syncthreads();

    int buf = 0;
    for (int k0 = 0; k0 < KDIM; k0 += BK) {
        const bool has_next = (k0 + BK) < KDIM;
        if (has_next) {
            int kn = k0 + BK;
            int nb = buf ^ 1;
            #pragma unroll
            for (int i = 0; i < 4; i++) {
                int row = a_row0 + i*32;
                cp16(asA + (nb*A_BUF_ELEMS + row*AS_STRIDE + a_cf)*4,
                     g_vox + (size_t)(m0 + row)*KDIM + kn + a_cf);
                int kr = b_kr0 + i*8;
                cp16(asB + (nb*B_BUF_ELEMS + kr*BS_STRIDE + b_n4)*4,
                     g_wl + (size_t)(kn + kr)*CH + n0 + b_n4);
            }
            cp_commit();
        }

        const uint32_t* Ab = Asm + buf*A_BUF_ELEMS;
        const uint32_t* Bb = Bsm + buf*B_BUF_ELEMS;
        #pragma unroll
        for (int kc = 0; kc < BK; kc += 8) {
            uint32_t a[4][4], b[4][2];
            #pragma unroll
            for (int mi = 0; mi < 4; mi++) {
                int r0 = mbase + mi*16 + g;
                a[mi][0] = Ab[(r0    )*AS_STRIDE + kc + tg];
                a[mi][1] = Ab[(r0 + 8)*AS_STRIDE + kc + tg];
                a[mi][2] = Ab[(r0    )*AS_STRIDE + kc + tg + 4];
                a[mi][3] = Ab[(r0 + 8)*AS_STRIDE + kc + tg + 4];
            }
            #pragma unroll
            for (int ni = 0; ni < 4; ni++) {
                int cn = nbase + ni*8 + g;
                b[ni][0] = Bb[(kc + tg    )*BS_STRIDE + cn];
                b[ni][1] = Bb[(kc + tg + 4)*BS_STRIDE + cn];
            }
            #pragma unroll
            for (int mi = 0; mi < 4; mi++)
                #pragma unroll
                for (int ni = 0; ni < 4; ni++)
                    mma_tf32(acc[mi][ni], a[mi], b[ni]);
        }

        if (has_next) {
            cp_wait0();
            __syncthreads();
            buf ^= 1;
        }
    }

    // Epilogue: bias + relu + transposed store
    const int bidx  = m0 / PLANE;
    const int mrel0 = m0 - bidx*PLANE + mbase;
    #pragma unroll
    for (int ni = 0; ni < 4; ni++) {
        int n_e = n0 + nbase + ni*8 + 2*tg;
        float be = bias[n_e];
        float bo = bias[n_e + 1];
        float* ope = out + ((size_t)(bidx*CH + n_e))*PLANE;
        float* opo = ope + PLANE;
        #pragma unroll
        for (int mi = 0; mi < 4; mi++) {
            int moff = mrel0 + mi*16 + g;
            ope[moff    ] = fmaxf(acc[mi][ni][0] + be, 0.f);
            opo[moff    ] = fmaxf(acc[mi][ni][1] + bo, 0.f);
            ope[moff + 8] = fmaxf(acc[mi][ni][2] + be, 0.f);
            opo[moff + 8] = fmaxf(acc[mi][ni][3] + bo, 0.f);
        }
    }
}

// ---------------------------------------------------------------------------
extern "C" void kernel_launch(void* const* d_in, const int* in_sizes, int n_in,
                              void* d_out, int out_size) {
    const float* features = (const float*)d_in[0];   // [2,128,48,160]
    const float* calib    = (const float*)d_in[1];   // [2,3,4]
    const float* corners  = (const float*)d_in[2];   // [1,5,161,161,3]
    const float* W_lin    = (const float*)d_in[3];   // [512,512]
    const float* b_lin    = (const float*)d_in[4];   // [512]
    float* out = (float*)d_out;                      // [2,512,160,160]

    cudaFuncSetAttribute(k_gemm, cudaFuncAttributeMaxDynamicSharedMemorySize,
                         GEMM_SMEM_BYTES);

    k_cumsum_w<<<BATCH*HH*2, 256>>>(features);
    k_cumsum_h<<<BATCH*WF, CC>>>();
    k_wperm<<<(KDIM*CH)/256, 256>>>(W_lin);
    k_bbox<<<NCELL/256, 256>>>(calib, corners);
    k_sample<<<NCELL/2, 256>>>();
    k_gemm<<<dim3(CH/BN, MROWS/BM), 256, GEMM_SMEM_BYTES>>>(b_lin, out);
}

// round 6
// speedup vs baseline: 3.5783x; 1.1688x over previous
#include <cuda_runtime.h>
#include <cuda_fp16.h>
#include <math.h>
#include <stdint.h>

// Problem constants
#define BATCH 2
#define CC    128
#define HH    48
#define WF    160
#define ND_   161
#define NW_   161
#define DD    160
#define WW    160
#define KDIM  512
#define CH    512
#define MROWS (BATCH*DD*WW)     // 51200
#define NCELL (BATCH*4*DD*WW)   // 204800
#define PLANE (WW*DD)           // 25600

// Static device scratch
__device__ float  g_integral[(size_t)BATCH*HH*WF*CC];  // NHWC
__device__ __half g_vox[(size_t)MROWS*KDIM];           // [M][K] fp16
__device__ __half g_wlT[(size_t)CH*KDIM];              // [N][K] permuted fp16
__device__ int    g_tidx[(size_t)16*NCELL];            // SoA: [tap][cell]
__device__ float  g_tw[(size_t)16*NCELL];              // SoA: [tap][cell]

// ---------------------------------------------------------------------------
// cumsum along W + transpose NCHW -> NHWC, via smem tile.
// ---------------------------------------------------------------------------
__global__ __launch_bounds__(256) void k_cumsum_w(const float* __restrict__ feat) {
    __shared__ float S[64][WF + 1];
    int blk = blockIdx.x;                 // 0..191
    int b    = blk / (HH*2);
    int rem  = blk % (HH*2);
    int h    = rem >> 1;
    int c0   = (rem & 1) * 64;
    int tid  = threadIdx.x;

    #pragma unroll
    for (int i = 0; i < 40; i++) {
        int idx = i*256 + tid;
        int c = idx / WF;
        int w = idx - c*WF;
        S[c][w] = feat[((size_t)(b*CC + c0 + c)*HH + h)*WF + w];
    }
    __syncthreads();
    if (tid < 64) {
        float acc = 0.f;
        #pragma unroll 8
        for (int w = 0; w < WF; w++) { acc += S[tid][w]; S[tid][w] = acc; }
    }
    __syncthreads();
    #pragma unroll
    for (int i = 0; i < 40; i++) {
        int idx = i*256 + tid;
        int w = idx >> 6;
        int c = idx & 63;
        g_integral[((size_t)(b*HH + h)*WF + w)*CC + c0 + c] = S[c][w];
    }
}

__global__ void k_cumsum_h() {
    int bw = blockIdx.x;
    int b = bw / WF, w = bw % WF;
    int c = threadIdx.x;
    float* p = g_integral + (((size_t)b*HH)*WF + w)*CC + c;
    const size_t stride = (size_t)WF*CC;
    float acc = 0.f;
    #pragma unroll 6
    for (int h = 0; h < HH; h++) {
        acc += p[h*stride];
        p[h*stride] = acc;
    }
}

// ---------------------------------------------------------------------------
// W permute+transpose+fp16:  g_wlT[n][kk] = half(W[(kk&127)*4 + (kk>>7)][n])
// ---------------------------------------------------------------------------
__global__ void k_wperm(const float* __restrict__ Wl) {
    int i = blockIdx.x*256 + threadIdx.x;       // 0..262143
    int n  = i >> 9;
    int kk = i & 511;
    int wrow = ((kk & 127) << 2) + (kk >> 7);
    g_wlT[i] = __float2half(Wl[(size_t)wrow*CH + n]);
}

// ---------------------------------------------------------------------------
// Per-cell bbox + 16 taps, SoA output.
// ---------------------------------------------------------------------------
__device__ __forceinline__ void project_pt(const float* __restrict__ cal,
                                           float X, float Y, float Z,
                                           float& nx, float& ny) {
    float h0 = cal[0]*X + cal[1]*Y + cal[2]*Z  + cal[3];
    float h1 = cal[4]*X + cal[5]*Y + cal[6]*Z  + cal[7];
    float h2 = cal[8]*X + cal[9]*Y + cal[10]*Z + cal[11];
    float ix = h0 / h2;
    float iy = h1 / h2;
    nx = fminf(fmaxf(2.0f*ix/(float)WF - 1.0f, -1.f), 1.f);
    ny = fminf(fmaxf(2.0f*iy/(float)HH - 1.0f, -1.f), 1.f);
}

__global__ void k_bbox(const float* __restrict__ calib,
                       const float* __restrict__ corners) {
    int cell = blockIdx.x*256 + threadIdx.x;
    if (cell >= NCELL) return;
    int w = cell % WW;
    int d = (cell / WW) % DD;
    int y = (cell / (WW*DD)) & 3;
    int b = cell / (WW*DD*4);
    const float* cal = calib + b*12;

    float ax, ay, bx, by, cx2, cy2, dx2, dy2;
    { const float* p = corners + (((size_t)y*ND_ + d)*NW_ + w)*3;
      project_pt(cal, p[0], p[1], p[2], ax, ay); }
    { const float* p = corners + (((size_t)y*ND_ + (d+1))*NW_ + w)*3;
      project_pt(cal, p[0], p[1], p[2], bx, by); }
    { const float* p = corners + (((size_t)(y+1)*ND_ + (d+1))*NW_ + (w+1))*3;
      project_pt(cal, p[0], p[1], p[2], cx2, cy2); }
    { const float* p = corners + (((size_t)(y+1)*ND_ + d)*NW_ + (w+1))*3;
      project_pt(cal, p[0], p[1], p[2], dx2, dy2); }

    float x0 = fminf(ax, bx),   y0v = fminf(ay, by);
    float x1 = fmaxf(cx2, dx2), y1v = fmaxf(cy2, dy2);

    float area = (x1 - x0) * (y1v - y0v) * ((float)HH * (float)WF * 0.25f) + 1e-6f;
    float vis  = (area > 1e-6f) ? 1.f : 0.f;
    float inv  = vis / area;

    float sx[4] = {x0, x1, x1, x0};
    float sy[4] = {y0v, y1v, y0v, y1v};
    float sg[4] = {1.f, 1.f, -1.f, -1.f};

    #pragma unroll
    for (int s = 0; s < 4; s++) {
        float gx = (sx[s] + 1.f)*((float)WF*0.5f) - 0.5f;
        float gy = (sy[s] + 1.f)*((float)HH*0.5f) - 0.5f;
        float x0f = floorf(gx), y0f = floorf(gy);
        float wx = gx - x0f, wy = gy - y0f;
        int ix = (int)x0f, iy = (int)y0f;
        float fw[4] = {(1.f-wx)*(1.f-wy), wx*(1.f-wy), (1.f-wx)*wy, wx*wy};
        int   tx[4] = {ix, ix+1, ix, ix+1};
        int   ty[4] = {iy, iy, iy+1, iy+1};
        #pragma unroll
        for (int t = 0; t < 4; t++) {
            int xx = tx[t], yy = ty[t];
            bool valid = (xx >= 0) & (xx < WF) & (yy >= 0) & (yy < HH);
            g_tidx[(size_t)(s*4 + t)*NCELL + cell] = valid ? ((b*HH + yy)*WF + xx)*CC : 0;
            g_tw  [(size_t)(s*4 + t)*NCELL + cell] = valid ? sg[s]*fw[t]*inv : 0.f;
        }
    }
}

// ---------------------------------------------------------------------------
// Sampler: per (cell, channel) up to 16 weighted gathers; zero-weight taps
// skipped (warp-uniform branch). Writes fp16 vox.
// ---------------------------------------------------------------------------
__global__ __launch_bounds__(256) void k_sample() {
    int cell = blockIdx.x*2 + (threadIdx.x >> 7);
    int c = threadIdx.x & 127;

    float acc = 0.f;
    #pragma unroll
    for (int i = 0; i < 16; i++) {
        float wgt = __ldg(&g_tw[(size_t)i*NCELL + cell]);
        if (wgt != 0.f) {
            int idx = __ldg(&g_tidx[(size_t)i*NCELL + cell]);
            acc += wgt * g_integral[idx + c];
        }
    }

    int w = cell % WW;
    int d = (cell / WW) % DD;
    int y = (cell / (WW*DD)) & 3;
    int b = cell / (WW*DD*4);
    int row = (b*WW + w)*DD + d;
    g_vox[(size_t)row*KDIM + y*CC + c] = __float2half(acc);
}

// ---------------------------------------------------------------------------
// fp16 tensor-core GEMM (mma.sync.m16n8k16): out = relu(vox@W + bias),
// fused transpose. 128x128x32 tile, 256 threads (2x4 warps, 64x32/warp),
// cp.async double buffer. A smem [M][K], B smem [N][K], stride 40 halves.
// ---------------------------------------------------------------------------
#define BM 128
#define BN 128
#define BK 32
#define KSTRIDE 40   // halves; 80B rows -> all fragment banks distinct

__device__ __forceinline__ void cp16(uint32_t smem, const void* gmem) {
    asm volatile("cp.async.ca.shared.global [%0], [%1], 16;\n" :: "r"(smem), "l"(gmem));
}
__device__ __forceinline__ void cp_commit() {
    asm volatile("cp.async.commit_group;\n" ::: "memory");
}
__device__ __forceinline__ void cp_wait0() {
    asm volatile("cp.async.wait_group 0;\n" ::: "memory");
}
__device__ __forceinline__ void mma_f16(float* c, const uint32_t* a, const uint32_t* b) {
    asm volatile(
        "mma.sync.aligned.m16n8k16.row.col.f32.f16.f16.f32 "
        "{%0,%1,%2,%3}, {%4,%5,%6,%7}, {%8,%9}, {%0,%1,%2,%3};\n"
        : "+f"(c[0]), "+f"(c[1]), "+f"(c[2]), "+f"(c[3])
        : "r"(a[0]), "r"(a[1]), "r"(a[2]), "r"(a[3]), "r"(b[0]), "r"(b[1]));
}

__global__ __launch_bounds__(256, 2) void k_gemm(const float* __restrict__ bias,
                                                 float* __restrict__ out) {
    __shared__ __align__(16) __half As[2][BM][KSTRIDE];
    __shared__ __align__(16) __half Bs[2][BN][KSTRIDE];

    const int n0 = blockIdx.x * BN;   // 4 blocks (fast axis)
    const int m0 = blockIdx.y * BM;   // 400 blocks
    const int tid = threadIdx.x;
    const int wid = tid >> 5;
    const int lane = tid & 31;
    const int g  = lane >> 2;
    const int tg = lane & 3;
    const int mbase = (wid >> 2) * 64;
    const int nbase = (wid & 3) * 32;

    // cp.async addressing: per thread 2 A chunks + 2 B chunks of 16B (8 halves)
    const int ld_row0 = tid >> 2;             // 0..63 (+64)
    const int ld_seg  = (tid & 3) * 8;        // half col 0,8,16,24

    uint32_t sA[2][2], sB[2][2];
    #pragma unroll
    for (int buf = 0; buf < 2; buf++)
        #pragma unroll
        for (int i = 0; i < 2; i++) {
            sA[buf][i] = (uint32_t)__cvta_generic_to_shared(&As[buf][ld_row0 + i*64][ld_seg]);
            sB[buf][i] = (uint32_t)__cvta_generic_to_shared(&Bs[buf][ld_row0 + i*64][ld_seg]);
        }

    float acc[4][4][4];
    #pragma unroll
    for (int mi = 0; mi < 4; mi++)
        #pragma unroll
        for (int ni = 0; ni < 4; ni++)
            #pragma unroll
            for (int r = 0; r < 4; r++) acc[mi][ni][r] = 0.f;

    // prologue: tile 0 -> buf 0
    #pragma unroll
    for (int i = 0; i < 2; i++) {
        cp16(sA[0][i], g_vox + (size_t)(m0 + ld_row0 + i*64)*KDIM + ld_seg);
        cp16(sB[0][i], g_wlT + (size_t)(n0 + ld_row0 + i*64)*KDIM + ld_seg);
    }
    cp_commit();
    cp_wait0();
    __syncthreads();

    int buf = 0;
    for (int k0 = 0; k0 < KDIM; k0 += BK) {
        const bool has_next = (k0 + BK) < KDIM;
        if (has_next) {
            int kn = k0 + BK;
            int nb = buf ^ 1;
            #pragma unroll
            for (int i = 0; i < 2; i++) {
                cp16(sA[nb][i], g_vox + (size_t)(m0 + ld_row0 + i*64)*KDIM + kn + ld_seg);
                cp16(sB[nb][i], g_wlT + (size_t)(n0 + ld_row0 + i*64)*KDIM + kn + ld_seg);
            }
            cp_commit();
        }

        #pragma unroll
        for (int kc = 0; kc < BK; kc += 16) {
            uint32_t a[4][4], b[4][2];
            #pragma unroll
            for (int mi = 0; mi < 4; mi++) {
                int r0 = mbase + mi*16 + g;
                a[mi][0] = *(const uint32_t*)&As[buf][r0    ][kc + 2*tg];
                a[mi][1] = *(const uint32_t*)&As[buf][r0 + 8][kc + 2*tg];
                a[mi][2] = *(const uint32_t*)&As[buf][r0    ][kc + 2*tg + 8];
                a[mi][3] = *(const uint32_t*)&As[buf][r0 + 8][kc + 2*tg + 8];
            }
            #pragma unroll
            for (int ni = 0; ni < 4; ni++) {
                int cn = nbase + ni*8 + g;
                b[ni][0] = *(const uint32_t*)&Bs[buf][cn][kc + 2*tg];
                b[ni][1] = *(const uint32_t*)&Bs[buf][cn][kc + 2*tg + 8];
            }
            #pragma unroll
            for (int mi = 0; mi < 4; mi++)
                #pragma unroll
                for (int ni = 0; ni < 4; ni++)
                    mma_f16(acc[mi][ni], a[mi], b[ni]);
        }

        if (has_next) {
            cp_wait0();
            __syncthreads();
            buf ^= 1;
        }
    }

    // Epilogue: bias + relu + transposed store (coalesced along M)
    const int bidx  = m0 / PLANE;
    const int mrel0 = m0 - bidx*PLANE + mbase;
    #pragma unroll
    for (int ni = 0; ni < 4; ni++) {
        int n_e = n0 + nbase + ni*8 + 2*tg;
        float be = bias[n_e];
        float bo = bias[n_e + 1];
        float* ope = out + ((size_t)(bidx*CH + n_e))*PLANE;
        float* opo = ope + PLANE;
        #pragma unroll
        for (int mi = 0; mi < 4; mi++) {
            int moff = mrel0 + mi*16 + g;
            ope[moff    ] = fmaxf(acc[mi][ni][0] + be, 0.f);
            opo[moff    ] = fmaxf(acc[mi][ni][1] + bo, 0.f);
            ope[moff + 8] = fmaxf(acc[mi][ni][2] + be, 0.f);
            opo[moff + 8] = fmaxf(acc[mi][ni][3] + bo, 0.f);
        }
    }
}

// ---------------------------------------------------------------------------
extern "C" void kernel_launch(void* const* d_in, const int* in_sizes, int n_in,
                              void* d_out, int out_size) {
    const float* features = (const float*)d_in[0];   // [2,128,48,160]
    const float* calib    = (const float*)d_in[1];   // [2,3,4]
    const float* corners  = (const float*)d_in[2];   // [1,5,161,161,3]
    const float* W_lin    = (const float*)d_in[3];   // [512,512]
    const float* b_lin    = (const float*)d_in[4];   // [512]
    float* out = (float*)d_out;                      // [2,512,160,160]

    k_cumsum_w<<<BATCH*HH*2, 256>>>(features);
    k_cumsum_h<<<BATCH*WF, CC>>>();
    k_wperm<<<(KDIM*CH)/256, 256>>>(W_lin);
    k_bbox<<<NCELL/256, 256>>>(calib, corners);
    k_sample<<<NCELL/2, 256>>>();
    k_gemm<<<dim3(CH/BN, MROWS/BM), 256>>>(b_lin, out);
}

// round 7
// speedup vs baseline: 5.9707x; 1.6686x over previous
#include <cuda_runtime.h>
#include <cuda_fp16.h>
#include <math.h>
#include <stdint.h>

// Problem constants
#define BATCH 2
#define CC    128
#define HH    48
#define WF    160
#define ND_   161
#define NW_   161
#define DD    160
#define WW    160
#define KDIM  512
#define CH    512
#define MROWS (BATCH*DD*WW)     // 51200
#define NCELL (BATCH*4*DD*WW)   // 204800
#define PLANE (WW*DD)           // 25600

// Static device scratch
__device__ float  g_integral[(size_t)BATCH*HH*WF*CC];  // NHWC
__device__ __half g_vox[(size_t)MROWS*KDIM];           // [M][K] fp16
__device__ __half g_wlT[(size_t)CH*KDIM];              // [N][K] permuted fp16
__device__ int    g_tidx[(size_t)16*NCELL];            // SoA: [tap][cell]
__device__ float  g_tw[(size_t)16*NCELL];              // SoA: [tap][cell]

// ---------------------------------------------------------------------------
// cumsum along W + transpose NCHW -> NHWC, via smem tile.
// ---------------------------------------------------------------------------
__global__ __launch_bounds__(256) void k_cumsum_w(const float* __restrict__ feat) {
    __shared__ float S[64][WF + 1];
    int blk = blockIdx.x;                 // 0..191
    int b    = blk / (HH*2);
    int rem  = blk % (HH*2);
    int h    = rem >> 1;
    int c0   = (rem & 1) * 64;
    int tid  = threadIdx.x;

    #pragma unroll
    for (int i = 0; i < 40; i++) {
        int idx = i*256 + tid;
        int c = idx / WF;
        int w = idx - c*WF;
        S[c][w] = feat[((size_t)(b*CC + c0 + c)*HH + h)*WF + w];
    }
    __syncthreads();
    if (tid < 64) {
        float acc = 0.f;
        #pragma unroll 8
        for (int w = 0; w < WF; w++) { acc += S[tid][w]; S[tid][w] = acc; }
    }
    __syncthreads();
    #pragma unroll
    for (int i = 0; i < 40; i++) {
        int idx = i*256 + tid;
        int w = idx >> 6;
        int c = idx & 63;
        g_integral[((size_t)(b*HH + h)*WF + w)*CC + c0 + c] = S[c][w];
    }
}

__global__ void k_cumsum_h() {
    int bw = blockIdx.x;
    int b = bw / WF, w = bw % WF;
    int c = threadIdx.x;
    float* p = g_integral + (((size_t)b*HH)*WF + w)*CC + c;
    const size_t stride = (size_t)WF*CC;
    float acc = 0.f;
    #pragma unroll 6
    for (int h = 0; h < HH; h++) {
        acc += p[h*stride];
        p[h*stride] = acc;
    }
}

// ---------------------------------------------------------------------------
// W permute+transpose+fp16:  g_wlT[n][kk] = half(W[(kk&127)*4 + (kk>>7)][n])
// ---------------------------------------------------------------------------
__global__ void k_wperm(const float* __restrict__ Wl) {
    int i = blockIdx.x*256 + threadIdx.x;       // 0..262143
    int n  = i >> 9;
    int kk = i & 511;
    int wrow = ((kk & 127) << 2) + (kk >> 7);
    g_wlT[i] = __float2half(Wl[(size_t)wrow*CH + n]);
}

// ---------------------------------------------------------------------------
// Per-cell bbox + 16 taps, SoA output.
// ---------------------------------------------------------------------------
__device__ __forceinline__ void project_pt(const float* __restrict__ cal,
                                           float X, float Y, float Z,
                                           float& nx, float& ny) {
    float h0 = cal[0]*X + cal[1]*Y + cal[2]*Z  + cal[3];
    float h1 = cal[4]*X + cal[5]*Y + cal[6]*Z  + cal[7];
    float h2 = cal[8]*X + cal[9]*Y + cal[10]*Z + cal[11];
    float ix = h0 / h2;
    float iy = h1 / h2;
    nx = fminf(fmaxf(2.0f*ix/(float)WF - 1.0f, -1.f), 1.f);
    ny = fminf(fmaxf(2.0f*iy/(float)HH - 1.0f, -1.f), 1.f);
}

__global__ void k_bbox(const float* __restrict__ calib,
                       const float* __restrict__ corners) {
    int cell = blockIdx.x*256 + threadIdx.x;
    if (cell >= NCELL) return;
    int w = cell % WW;
    int d = (cell / WW) % DD;
    int y = (cell / (WW*DD)) & 3;
    int b = cell / (WW*DD*4);
    const float* cal = calib + b*12;

    float ax, ay, bx, by, cx2, cy2, dx2, dy2;
    { const float* p = corners + (((size_t)y*ND_ + d)*NW_ + w)*3;
      project_pt(cal, p[0], p[1], p[2], ax, ay); }
    { const float* p = corners + (((size_t)y*ND_ + (d+1))*NW_ + w)*3;
      project_pt(cal, p[0], p[1], p[2], bx, by); }
    { const float* p = corners + (((size_t)(y+1)*ND_ + (d+1))*NW_ + (w+1))*3;
      project_pt(cal, p[0], p[1], p[2], cx2, cy2); }
    { const float* p = corners + (((size_t)(y+1)*ND_ + d)*NW_ + (w+1))*3;
      project_pt(cal, p[0], p[1], p[2], dx2, dy2); }

    float x0 = fminf(ax, bx),   y0v = fminf(ay, by);
    float x1 = fmaxf(cx2, dx2), y1v = fmaxf(cy2, dy2);

    float area = (x1 - x0) * (y1v - y0v) * ((float)HH * (float)WF * 0.25f) + 1e-6f;
    float vis  = (area > 1e-6f) ? 1.f : 0.f;
    float inv  = vis / area;

    float sx[4] = {x0, x1, x1, x0};
    float sy[4] = {y0v, y1v, y0v, y1v};
    float sg[4] = {1.f, 1.f, -1.f, -1.f};

    #pragma unroll
    for (int s = 0; s < 4; s++) {
        float gx = (sx[s] + 1.f)*((float)WF*0.5f) - 0.5f;
        float gy = (sy[s] + 1.f)*((float)HH*0.5f) - 0.5f;
        float x0f = floorf(gx), y0f = floorf(gy);
        float wx = gx - x0f, wy = gy - y0f;
        int ix = (int)x0f, iy = (int)y0f;
        float fw[4] = {(1.f-wx)*(1.f-wy), wx*(1.f-wy), (1.f-wx)*wy, wx*wy};
        int   tx[4] = {ix, ix+1, ix, ix+1};
        int   ty[4] = {iy, iy, iy+1, iy+1};
        #pragma unroll
        for (int t = 0; t < 4; t++) {
            int xx = tx[t], yy = ty[t];
            bool valid = (xx >= 0) & (xx < WF) & (yy >= 0) & (yy < HH);
            g_tidx[(size_t)(s*4 + t)*NCELL + cell] = valid ? ((b*HH + yy)*WF + xx)*CC : 0;
            g_tw  [(size_t)(s*4 + t)*NCELL + cell] = valid ? sg[s]*fw[t]*inv : 0.f;
        }
    }
}

// ---------------------------------------------------------------------------
// Sampler: 32 threads per cell, float4 per thread (4 channels). Zero-weight
// taps skipped (warp-uniform). Writes fp16 vox (8B per thread).
// ---------------------------------------------------------------------------
__global__ __launch_bounds__(256) void k_sample() {
    int cell = blockIdx.x*8 + (threadIdx.x >> 5);
    int c4 = (threadIdx.x & 31) * 4;

    float4 acc = make_float4(0.f, 0.f, 0.f, 0.f);
    #pragma unroll
    for (int i = 0; i < 16; i++) {
        float wgt = __ldg(&g_tw[(size_t)i*NCELL + cell]);
        if (wgt != 0.f) {
            int idx = __ldg(&g_tidx[(size_t)i*NCELL + cell]);
            float4 v = *(const float4*)&g_integral[idx + c4];
            acc.x += wgt * v.x;
            acc.y += wgt * v.y;
            acc.z += wgt * v.z;
            acc.w += wgt * v.w;
        }
    }

    int w = cell % WW;
    int d = (cell / WW) % DD;
    int y = (cell / (WW*DD)) & 3;
    int b = cell / (WW*DD*4);
    int row = (b*WW + w)*DD + d;
    __half2 lo = __floats2half2_rn(acc.x, acc.y);
    __half2 hi = __floats2half2_rn(acc.z, acc.w);
    uint2 pk;
    pk.x = *(uint32_t*)&lo;
    pk.y = *(uint32_t*)&hi;
    *(uint2*)&g_vox[(size_t)row*KDIM + y*CC + c4] = pk;
}

// ---------------------------------------------------------------------------
// fp16 tensor-core GEMM (mma.sync.m16n8k16 + ldmatrix):
// out = relu(vox@W + bias), fused transpose. 128x128x32 tile, 256 threads
// (2x4 warps, 64x32/warp), cp.async double buffer.
// A smem [M][K], B smem [N][K], stride 40 halves (conflict-free ldmatrix).
// ---------------------------------------------------------------------------
#define BM 128
#define BN 128
#define BK 32
#define KSTRIDE 40   // halves; 80B rows
#define ABUF_BYTES (BM*KSTRIDE*2)

__device__ __forceinline__ void cp16(uint32_t smem, const void* gmem) {
    asm volatile("cp.async.ca.shared.global [%0], [%1], 16;\n" :: "r"(smem), "l"(gmem));
}
__device__ __forceinline__ void cp_commit() {
    asm volatile("cp.async.commit_group;\n" ::: "memory");
}
__device__ __forceinline__ void cp_wait0() {
    asm volatile("cp.async.wait_group 0;\n" ::: "memory");
}
__device__ __forceinline__ void ldsm_x4(uint32_t& r0, uint32_t& r1,
                                        uint32_t& r2, uint32_t& r3, uint32_t addr) {
    asm volatile("ldmatrix.sync.aligned.m8n8.x4.shared.b16 {%0,%1,%2,%3}, [%4];"
                 : "=r"(r0), "=r"(r1), "=r"(r2), "=r"(r3) : "r"(addr));
}
__device__ __forceinline__ void mma_f16(float* c, const uint32_t* a, const uint32_t* b) {
    asm volatile(
        "mma.sync.aligned.m16n8k16.row.col.f32.f16.f16.f32 "
        "{%0,%1,%2,%3}, {%4,%5,%6,%7}, {%8,%9}, {%0,%1,%2,%3};\n"
        : "+f"(c[0]), "+f"(c[1]), "+f"(c[2]), "+f"(c[3])
        : "r"(a[0]), "r"(a[1]), "r"(a[2]), "r"(a[3]), "r"(b[0]), "r"(b[1]));
}

__global__ __launch_bounds__(256, 2) void k_gemm(const float* __restrict__ bias,
                                                 float* __restrict__ out) {
    __shared__ __align__(16) __half As[2][BM][KSTRIDE];
    __shared__ __align__(16) __half Bs[2][BN][KSTRIDE];

    const int n0 = blockIdx.x * BN;   // 4 blocks (fast axis)
    const int m0 = blockIdx.y * BM;   // 400 blocks
    const int tid = threadIdx.x;
    const int wid = tid >> 5;
    const int lane = tid & 31;
    const int g  = lane >> 2;
    const int tg = lane & 3;
    const int mbase = (wid >> 2) * 64;
    const int nbase = (wid & 3) * 32;

    // cp.async addressing: per thread 2 A chunks + 2 B chunks of 16B
    const int ld_row0 = tid >> 2;             // 0..63 (+64)
    const int ld_seg  = (tid & 3) * 8;        // half col 0,8,16,24

    uint32_t sA[2][2], sB[2][2];
    #pragma unroll
    for (int buf = 0; buf < 2; buf++)
        #pragma unroll
        for (int i = 0; i < 2; i++) {
            sA[buf][i] = (uint32_t)__cvta_generic_to_shared(&As[buf][ld_row0 + i*64][ld_seg]);
            sB[buf][i] = (uint32_t)__cvta_generic_to_shared(&Bs[buf][ld_row0 + i*64][ld_seg]);
        }

    // ldmatrix addresses (buf 0; add ABUF_BYTES for buf 1, kc*2 for kc)
    // A .x4 for tile (mbase+mi*16, kc): lane row = (lane&15), col = ((lane>>4)<<3)
    uint32_t lmA[4];
    #pragma unroll
    for (int mi = 0; mi < 4; mi++)
        lmA[mi] = (uint32_t)__cvta_generic_to_shared(
            &As[0][mbase + mi*16 + (lane & 15)][(lane >> 4) << 3]);
    // B .x4 for n-pair p (16 n rows x 16 k):
    // nrow = nbase + p*16 + ((lane>>4)&1)*8 + (lane&7), col = ((lane>>3)&1)*8
    uint32_t lmB[2];
    #pragma unroll
    for (int p = 0; p < 2; p++)
        lmB[p] = (uint32_t)__cvta_generic_to_shared(
            &Bs[0][nbase + p*16 + (((lane >> 4) & 1) << 3) + (lane & 7)]
               [((lane >> 3) & 1) << 3]);

    float acc[4][4][4];
    #pragma unroll
    for (int mi = 0; mi < 4; mi++)
        #pragma unroll
        for (int ni = 0; ni < 4; ni++)
            #pragma unroll
            for (int r = 0; r < 4; r++) acc[mi][ni][r] = 0.f;

    // prologue: tile 0 -> buf 0
    #pragma unroll
    for (int i = 0; i < 2; i++) {
        cp16(sA[0][i], g_vox + (size_t)(m0 + ld_row0 + i*64)*KDIM + ld_seg);
        cp16(sB[0][i], g_wlT + (size_t)(n0 + ld_row0 + i*64)*KDIM + ld_seg);
    }
    cp_commit();
    cp_wait0();
    __syncthreads();

    int buf = 0;
    for (int k0 = 0; k0 < KDIM; k0 += BK) {
        const bool has_next = (k0 + BK) < KDIM;
        if (has_next) {
            int kn = k0 + BK;
            int nb = buf ^ 1;
            #pragma unroll
            for (int i = 0; i < 2; i++) {
                cp16(sA[nb][i], g_vox + (size_t)(m0 + ld_row0 + i*64)*KDIM + kn + ld_seg);
                cp16(sB[nb][i], g_wlT + (size_t)(n0 + ld_row0 + i*64)*KDIM + kn + ld_seg);
            }
            cp_commit();
        }

        const uint32_t bofs = (uint32_t)buf * ABUF_BYTES;
        #pragma unroll
        for (int kc = 0; kc < BK; kc += 16) {
            uint32_t a[4][4], b[4][2];
            #pragma unroll
            for (int mi = 0; mi < 4; mi++)
                ldsm_x4(a[mi][0], a[mi][1], a[mi][2], a[mi][3],
                        lmA[mi] + bofs + kc*2);
            #pragma unroll
            for (int p = 0; p < 2; p++)
                ldsm_x4(b[2*p][0], b[2*p][1], b[2*p+1][0], b[2*p+1][1],
                        lmB[p] + bofs + kc*2);
            #pragma unroll
            for (int mi = 0; mi < 4; mi++)
                #pragma unroll
                for (int ni = 0; ni < 4; ni++)
                    mma_f16(acc[mi][ni], a[mi], b[ni]);
        }

        if (has_next) {
            cp_wait0();
            __syncthreads();
            buf ^= 1;
        }
    }

    // Epilogue: bias + relu + transposed store (coalesced along M)
    const int bidx  = m0 / PLANE;
    const int mrel0 = m0 - bidx*PLANE + mbase;
    #pragma unroll
    for (int ni = 0; ni < 4; ni++) {
        int n_e = n0 + nbase + ni*8 + 2*tg;
        float be = bias[n_e];
        float bo = bias[n_e + 1];
        float* ope = out + ((size_t)(bidx*CH + n_e))*PLANE;
        float* opo = ope + PLANE;
        #pragma unroll
        for (int mi = 0; mi < 4; mi++) {
            int moff = mrel0 + mi*16 + g;
            ope[moff    ] = fmaxf(acc[mi][ni][0] + be, 0.f);
            opo[moff    ] = fmaxf(acc[mi][ni][1] + bo, 0.f);
            ope[moff + 8] = fmaxf(acc[mi][ni][2] + be, 0.f);
            opo[moff + 8] = fmaxf(acc[mi][ni][3] + bo, 0.f);
        }
    }
}

// ---------------------------------------------------------------------------
extern "C" void kernel_launch(void* const* d_in, const int* in_sizes, int n_in,
                              void* d_out, int out_size) {
    const float* features = (const float*)d_in[0];   // [2,128,48,160]
    const float* calib    = (const float*)d_in[1];   // [2,3,4]
    const float* corners  = (const float*)d_in[2];   // [1,5,161,161,3]
    const float* W_lin    = (const float*)d_in[3];   // [512,512]
    const float* b_lin    = (const float*)d_in[4];   // [512]
    float* out = (float*)d_out;                      // [2,512,160,160]

    k_cumsum_w<<<BATCH*HH*2, 256>>>(features);
    k_cumsum_h<<<BATCH*WF, CC>>>();
    k_wperm<<<(KDIM*CH)/256, 256>>>(W_lin);
    k_bbox<<<NCELL/256, 256>>>(calib, corners);
    k_sample<<<NCELL/8, 256>>>();
    k_gemm<<<dim3(CH/BN, MROWS/BM), 256>>>(b_lin, out);
}

// round 8
// speedup vs baseline: 6.1526x; 1.0305x over previous
#include <cuda_runtime.h>
#include <cuda_fp16.h>
#include <math.h>
#include <stdint.h>

// Problem constants
#define BATCH 2
#define CC    128
#define HH    48
#define WF    160
#define ND_   161
#define NW_   161
#define DD    160
#define WW    160
#define KDIM  512
#define CH    512
#define MROWS (BATCH*DD*WW)     // 51200
#define NCELL (BATCH*4*DD*WW)   // 204800
#define PLANE (WW*DD)           // 25600

// Static device scratch
__device__ float  g_integral[(size_t)BATCH*HH*WF*CC];  // NHWC
__device__ __half g_vox[(size_t)MROWS*KDIM];           // [M][K] fp16
__device__ __half g_wlT[(size_t)CH*KDIM];              // [N][K] permuted fp16
__device__ int    g_tidx[(size_t)16*NCELL];            // SoA: [tap][cell]
__device__ float  g_tw[(size_t)16*NCELL];              // SoA: [tap][cell]

// ---------------------------------------------------------------------------
// cumsum along W + transpose NCHW -> NHWC, via smem tile.
// ---------------------------------------------------------------------------
__global__ __launch_bounds__(256) void k_cumsum_w(const float* __restrict__ feat) {
    __shared__ float S[64][WF + 1];
    int blk = blockIdx.x;                 // 0..191
    int b    = blk / (HH*2);
    int rem  = blk % (HH*2);
    int h    = rem >> 1;
    int c0   = (rem & 1) * 64;
    int tid  = threadIdx.x;

    #pragma unroll
    for (int i = 0; i < 40; i++) {
        int idx = i*256 + tid;
        int c = idx / WF;
        int w = idx - c*WF;
        S[c][w] = feat[((size_t)(b*CC + c0 + c)*HH + h)*WF + w];
    }
    __syncthreads();
    if (tid < 64) {
        float acc = 0.f;
        #pragma unroll 8
        for (int w = 0; w < WF; w++) { acc += S[tid][w]; S[tid][w] = acc; }
    }
    __syncthreads();
    #pragma unroll
    for (int i = 0; i < 40; i++) {
        int idx = i*256 + tid;
        int w = idx >> 6;
        int c = idx & 63;
        g_integral[((size_t)(b*HH + h)*WF + w)*CC + c0 + c] = S[c][w];
    }
}

__global__ void k_cumsum_h() {
    int bw = blockIdx.x;
    int b = bw / WF, w = bw % WF;
    int c = threadIdx.x;
    float* p = g_integral + (((size_t)b*HH)*WF + w)*CC + c;
    const size_t stride = (size_t)WF*CC;
    float acc = 0.f;
    #pragma unroll 6
    for (int h = 0; h < HH; h++) {
        acc += p[h*stride];
        p[h*stride] = acc;
    }
}

// ---------------------------------------------------------------------------
// W permute+transpose+fp16:  g_wlT[n][kk] = half(W[(kk&127)*4 + (kk>>7)][n])
// ---------------------------------------------------------------------------
__global__ void k_wperm(const float* __restrict__ Wl) {
    int i = blockIdx.x*256 + threadIdx.x;       // 0..262143
    int n  = i >> 9;
    int kk = i & 511;
    int wrow = ((kk & 127) << 2) + (kk >> 7);
    g_wlT[i] = __float2half(Wl[(size_t)wrow*CH + n]);
}

// ---------------------------------------------------------------------------
// Per-cell bbox + 16 taps, SoA output.
// ---------------------------------------------------------------------------
__device__ __forceinline__ void project_pt(const float* __restrict__ cal,
                                           float X, float Y, float Z,
                                           float& nx, float& ny) {
    float h0 = cal[0]*X + cal[1]*Y + cal[2]*Z  + cal[3];
    float h1 = cal[4]*X + cal[5]*Y + cal[6]*Z  + cal[7];
    float h2 = cal[8]*X + cal[9]*Y + cal[10]*Z + cal[11];
    float ix = h0 / h2;
    float iy = h1 / h2;
    nx = fminf(fmaxf(2.0f*ix/(float)WF - 1.0f, -1.f), 1.f);
    ny = fminf(fmaxf(2.0f*iy/(float)HH - 1.0f, -1.f), 1.f);
}

__global__ void k_bbox(const float* __restrict__ calib,
                       const float* __restrict__ corners) {
    int cell = blockIdx.x*256 + threadIdx.x;
    if (cell >= NCELL) return;
    int w = cell % WW;
    int d = (cell / WW) % DD;
    int y = (cell / (WW*DD)) & 3;
    int b = cell / (WW*DD*4);
    const float* cal = calib + b*12;

    float ax, ay, bx, by, cx2, cy2, dx2, dy2;
    { const float* p = corners + (((size_t)y*ND_ + d)*NW_ + w)*3;
      project_pt(cal, p[0], p[1], p[2], ax, ay); }
    { const float* p = corners + (((size_t)y*ND_ + (d+1))*NW_ + w)*3;
      project_pt(cal, p[0], p[1], p[2], bx, by); }
    { const float* p = corners + (((size_t)(y+1)*ND_ + (d+1))*NW_ + (w+1))*3;
      project_pt(cal, p[0], p[1], p[2], cx2, cy2); }
    { const float* p = corners + (((size_t)(y+1)*ND_ + d)*NW_ + (w+1))*3;
      project_pt(cal, p[0], p[1], p[2], dx2, dy2); }

    float x0 = fminf(ax, bx),   y0v = fminf(ay, by);
    float x1 = fmaxf(cx2, dx2), y1v = fmaxf(cy2, dy2);

    float area = (x1 - x0) * (y1v - y0v) * ((float)HH * (float)WF * 0.25f) + 1e-6f;
    float vis  = (area > 1e-6f) ? 1.f : 0.f;
    float inv  = vis / area;

    float sx[4] = {x0, x1, x1, x0};
    float sy[4] = {y0v, y1v, y0v, y1v};
    float sg[4] = {1.f, 1.f, -1.f, -1.f};

    #pragma unroll
    for (int s = 0; s < 4; s++) {
        float gx = (sx[s] + 1.f)*((float)WF*0.5f) - 0.5f;
        float gy = (sy[s] + 1.f)*((float)HH*0.5f) - 0.5f;
        float x0f = floorf(gx), y0f = floorf(gy);
        float wx = gx - x0f, wy = gy - y0f;
        int ix = (int)x0f, iy = (int)y0f;
        float fw[4] = {(1.f-wx)*(1.f-wy), wx*(1.f-wy), (1.f-wx)*wy, wx*wy};
        int   tx[4] = {ix, ix+1, ix, ix+1};
        int   ty[4] = {iy, iy, iy+1, iy+1};
        #pragma unroll
        for (int t = 0; t < 4; t++) {
            int xx = tx[t], yy = ty[t];
            bool valid = (xx >= 0) & (xx < WF) & (yy >= 0) & (yy < HH);
            g_tidx[(size_t)(s*4 + t)*NCELL + cell] = valid ? ((b*HH + yy)*WF + xx)*CC : 0;
            g_tw  [(size_t)(s*4 + t)*NCELL + cell] = valid ? sg[s]*fw[t]*inv : 0.f;
        }
    }
}

// ---------------------------------------------------------------------------
// Sampler: 32 threads per cell, float4 per thread (4 channels). Zero-weight
// taps skipped (warp-uniform). Writes fp16 vox (8B per thread).
// ---------------------------------------------------------------------------
__global__ __launch_bounds__(256) void k_sample() {
    int cell = blockIdx.x*8 + (threadIdx.x >> 5);
    int c4 = (threadIdx.x & 31) * 4;

    float4 acc = make_float4(0.f, 0.f, 0.f, 0.f);
    #pragma unroll
    for (int i = 0; i < 16; i++) {
        float wgt = __ldg(&g_tw[(size_t)i*NCELL + cell]);
        if (wgt != 0.f) {
            int idx = __ldg(&g_tidx[(size_t)i*NCELL + cell]);
            float4 v = *(const float4*)&g_integral[idx + c4];
            acc.x += wgt * v.x;
            acc.y += wgt * v.y;
            acc.z += wgt * v.z;
            acc.w += wgt * v.w;
        }
    }

    int w = cell % WW;
    int d = (cell / WW) % DD;
    int y = (cell / (WW*DD)) & 3;
    int b = cell / (WW*DD*4);
    int row = (b*WW + w)*DD + d;
    __half2 lo = __floats2half2_rn(acc.x, acc.y);
    __half2 hi = __floats2half2_rn(acc.z, acc.w);
    uint2 pk;
    pk.x = *(uint32_t*)&lo;
    pk.y = *(uint32_t*)&hi;
    *(uint2*)&g_vox[(size_t)row*KDIM + y*CC + c4] = pk;
}

// ---------------------------------------------------------------------------
// fp16 tensor-core GEMM (mma.sync.m16n8k16 + ldmatrix), 3-stage cp.async
// pipeline. out = relu(vox@W + bias), fused transpose. 128x128x32 tile,
// 256 threads (2x4 warps, 64x32/warp). A smem [M][K], B smem [N][K],
// stride 40 halves. Dynamic smem: 3 stages x (A+B).
// ---------------------------------------------------------------------------
#define BM 128
#define BN 128
#define BK 32
#define KSTRIDE 40                       // halves; 80B rows
#define ABUF_BYTES (BM*KSTRIDE*2)        // 10240 (one A or B stage)
#define STAGE_BYTES (2*ABUF_BYTES)       // 20480
#define NSTAGE 3
#define GEMM_SMEM (NSTAGE*STAGE_BYTES)   // 61440

__device__ __forceinline__ void cp16(uint32_t smem, const void* gmem) {
    asm volatile("cp.async.ca.shared.global [%0], [%1], 16;\n" :: "r"(smem), "l"(gmem));
}
__device__ __forceinline__ void cp_commit() {
    asm volatile("cp.async.commit_group;\n" ::: "memory");
}
template<int N> __device__ __forceinline__ void cp_wait() {
    asm volatile("cp.async.wait_group %0;\n" :: "n"(N) : "memory");
}
__device__ __forceinline__ void ldsm_x4(uint32_t& r0, uint32_t& r1,
                                        uint32_t& r2, uint32_t& r3, uint32_t addr) {
    asm volatile("ldmatrix.sync.aligned.m8n8.x4.shared.b16 {%0,%1,%2,%3}, [%4];"
                 : "=r"(r0), "=r"(r1), "=r"(r2), "=r"(r3) : "r"(addr));
}
__device__ __forceinline__ void mma_f16(float* c, const uint32_t* a, const uint32_t* b) {
    asm volatile(
        "mma.sync.aligned.m16n8k16.row.col.f32.f16.f16.f32 "
        "{%0,%1,%2,%3}, {%4,%5,%6,%7}, {%8,%9}, {%0,%1,%2,%3};\n"
        : "+f"(c[0]), "+f"(c[1]), "+f"(c[2]), "+f"(c[3])
        : "r"(a[0]), "r"(a[1]), "r"(a[2]), "r"(a[3]), "r"(b[0]), "r"(b[1]));
}

__global__ __launch_bounds__(256, 2) void k_gemm(const float* __restrict__ bias,
                                                 float* __restrict__ out) {
    extern __shared__ __align__(16) __half smem[];
    // stage s: A at s*STAGE_BYTES, B at s*STAGE_BYTES + ABUF_BYTES (bytes)

    const int n0 = blockIdx.x * BN;   // 4 blocks (fast axis)
    const int m0 = blockIdx.y * BM;   // 400 blocks
    const int tid = threadIdx.x;
    const int wid = tid >> 5;
    const int lane = tid & 31;
    const int g  = lane >> 2;
    const int tg = lane & 3;
    const int mbase = (wid >> 2) * 64;
    const int nbase = (wid & 3) * 32;

    const uint32_t smem_base = (uint32_t)__cvta_generic_to_shared(smem);

    // cp.async addressing: per thread 2 A chunks + 2 B chunks of 16B
    const int ld_row0 = tid >> 2;             // 0..63 (+64)
    const int ld_seg  = (tid & 3) * 8;        // half col 0,8,16,24
    const uint32_t stA0 = smem_base + (uint32_t)(ld_row0*KSTRIDE + ld_seg)*2;
    const uint32_t stA1 = smem_base + (uint32_t)((ld_row0+64)*KSTRIDE + ld_seg)*2;
    const uint32_t stB0 = stA0 + ABUF_BYTES;
    const uint32_t stB1 = stA1 + ABUF_BYTES;

    // ldmatrix base addresses (stage 0)
    uint32_t lmA[4];
    #pragma unroll
    for (int mi = 0; mi < 4; mi++)
        lmA[mi] = smem_base +
            (uint32_t)((mbase + mi*16 + (lane & 15))*KSTRIDE + ((lane >> 4) << 3))*2;
    uint32_t lmB[2];
    #pragma unroll
    for (int p = 0; p < 2; p++)
        lmB[p] = smem_base + ABUF_BYTES +
            (uint32_t)((nbase + p*16 + (((lane >> 4) & 1) << 3) + (lane & 7))*KSTRIDE
                       + (((lane >> 3) & 1) << 3))*2;

    float acc[4][4][4];
    #pragma unroll
    for (int mi = 0; mi < 4; mi++)
        #pragma unroll
        for (int ni = 0; ni < 4; ni++)
            #pragma unroll
            for (int r = 0; r < 4; r++) acc[mi][ni][r] = 0.f;

    auto load_chunk = [&](int c) {
        uint32_t so = (uint32_t)(c % NSTAGE) * STAGE_BYTES;
        int kb = c * BK;
        cp16(stA0 + so, g_vox + (size_t)(m0 + ld_row0)*KDIM + kb + ld_seg);
        cp16(stA1 + so, g_vox + (size_t)(m0 + ld_row0 + 64)*KDIM + kb + ld_seg);
        cp16(stB0 + so, g_wlT + (size_t)(n0 + ld_row0)*KDIM + kb + ld_seg);
        cp16(stB1 + so, g_wlT + (size_t)(n0 + ld_row0 + 64)*KDIM + kb + ld_seg);
        cp_commit();
    };

    const int NCHUNK = KDIM / BK;     // 16
    load_chunk(0);
    load_chunk(1);

    for (int c = 0; c < NCHUNK; c++) {
        cp_wait<1>();                 // chunk c resident (c+1 may be in flight)
        __syncthreads();              // also guards WAR on stage (c+2)%3

        if (c + 2 < NCHUNK) load_chunk(c + 2);

        const uint32_t so = (uint32_t)(c % NSTAGE) * STAGE_BYTES;
        #pragma unroll
        for (int kc = 0; kc < BK; kc += 16) {
            uint32_t a[4][4], b[4][2];
            #pragma unroll
            for (int mi = 0; mi < 4; mi++)
                ldsm_x4(a[mi][0], a[mi][1], a[mi][2], a[mi][3],
                        lmA[mi] + so + kc*2);
            #pragma unroll
            for (int p = 0; p < 2; p++)
                ldsm_x4(b[2*p][0], b[2*p][1], b[2*p+1][0], b[2*p+1][1],
                        lmB[p] + so + kc*2);
            #pragma unroll
            for (int mi = 0; mi < 4; mi++)
                #pragma unroll
                for (int ni = 0; ni < 4; ni++)
                    mma_f16(acc[mi][ni], a[mi], b[ni]);
        }
    }

    // Epilogue: bias + relu + transposed store (coalesced along M)
    const int bidx  = m0 / PLANE;
    const int mrel0 = m0 - bidx*PLANE + mbase;
    #pragma unroll
    for (int ni = 0; ni < 4; ni++) {
        int n_e = n0 + nbase + ni*8 + 2*tg;
        float be = bias[n_e];
        float bo = bias[n_e + 1];
        float* ope = out + ((size_t)(bidx*CH + n_e))*PLANE;
        float* opo = ope + PLANE;
        #pragma unroll
        for (int mi = 0; mi < 4; mi++) {
            int moff = mrel0 + mi*16 + g;
            ope[moff    ] = fmaxf(acc[mi][ni][0] + be, 0.f);
            opo[moff    ] = fmaxf(acc[mi][ni][1] + bo, 0.f);
            ope[moff + 8] = fmaxf(acc[mi][ni][2] + be, 0.f);
            opo[moff + 8] = fmaxf(acc[mi][ni][3] + bo, 0.f);
        }
    }
}

// ---------------------------------------------------------------------------
extern "C" void kernel_launch(void* const* d_in, const int* in_sizes, int n_in,
                              void* d_out, int out_size) {
    const float* features = (const float*)d_in[0];   // [2,128,48,160]
    const float* calib    = (const float*)d_in[1];   // [2,3,4]
    const float* corners  = (const float*)d_in[2];   // [1,5,161,161,3]
    const float* W_lin    = (const float*)d_in[3];   // [512,512]
    const float* b_lin    = (const float*)d_in[4];   // [512]
    float* out = (float*)d_out;                      // [2,512,160,160]

    cudaFuncSetAttribute(k_gemm, cudaFuncAttributeMaxDynamicSharedMemorySize,
                         GEMM_SMEM);

    // Order chosen so k_sample is the 4th launch (ncu -s window captures it).
    k_cumsum_w<<<BATCH*HH*2, 256>>>(features);
    k_cumsum_h<<<BATCH*WF, CC>>>();
    k_bbox<<<NCELL/256, 256>>>(calib, corners);
    k_sample<<<NCELL/8, 256>>>();
    k_wperm<<<(KDIM*CH)/256, 256>>>(W_lin);
    k_gemm<<<dim3(CH/BN, MROWS/BM), 256, GEMM_SMEM>>>(b_lin, out);
}